// round 15
// baseline (speedup 1.0000x reference)
#include <cuda_runtime.h>
#include <cuda_fp16.h>
#include <cstdint>
#include <cstddef>

// NeRD pixel decoder — fp16 mma.sync m16n8k16, ldmatrix.x4, cp.async.
// R14: M-split for occupancy. One CTA = (batch, row, half-row): M=64 pixels,
// full N=256, fully fused (MLP is per-pixel, so M-split preserves fusion).
// 2 CTAs/SM (__launch_bounds__(256,2), 95.2 KB smem/CTA) -> cross-CTA overlap
// hides barrier/LDSM latency that single-CTA lockstep exposed (occ was 12.4%).
//   Layer 0: [64 x 3200] @ [3200 x 256] as 100 K=32 slabs (25 taps x 4 cquads)
//   Layers 1,2: [64 x 256] @ [256 x 256] as 8 K=32 slabs
//   Head: [64 x 256] @ [256 x 3] scalar
// Weights pre-scaled by 2^8 (exact); epilogue multiplies acc by 2^-8.
//
// Bank checks (ldsm 8-row wavefronts, 16B rows):
//   A/B slabs stride 40 halves = 20 words: banks {(20r ..+3) mod 32} distinct
//   smH stride 264 halves = 132 words (≡4 mod 32): distinct

#define FC   128
#define HID  256
#define OUTC 3
#define IMH  128
#define IMW  128
#define OMEGA 30.0f
#define THREADS 256
#define WSCALE 256.0f
#define INV_WSCALE 0.00390625f

#define SMH_H 264
#define SMA_H 40
#define SMB_H 40
#define SMH_HALF (64 * SMH_H)       // 16896
#define SMA_HALF (72 * SMA_H)       // 2880 (68 rows used; x2 alias into smH)
#define SMB_HALF (256 * SMB_H)      // 10240
#define OFF_B(st) (SMH_HALF + (st) * SMB_HALF)
#define SMEM_BYTES ((SMH_HALF + 3 * SMB_HALF) * 2)   // 95232 B

// ---- persistent scratch: pre-tiled fp16, contiguous per K=32 slab ----
__device__ __half g_xiA[2 * 4 * 132 * 132 * 32];   // [((b*4+cq)*132+hp)][wa*32+kc]
__device__ __half g_W0s[25 * 4 * 256 * 32];        // [(tap*4+cq)*256+n][kc] *2^8
__device__ __half g_W1s[8 * 256 * 32];             // [(kb*256+n)][kc]      *2^8
__device__ __half g_W2s[8 * 256 * 32];

__device__ __forceinline__ void mma16(float* c, const unsigned* a, unsigned b0, unsigned b1) {
    asm("mma.sync.aligned.m16n8k16.row.col.f32.f16.f16.f32 "
        "{%0,%1,%2,%3}, {%4,%5,%6,%7}, {%8,%9}, {%0,%1,%2,%3};"
        : "+f"(c[0]), "+f"(c[1]), "+f"(c[2]), "+f"(c[3])
        : "r"(a[0]), "r"(a[1]), "r"(a[2]), "r"(a[3]), "r"(b0), "r"(b1));
}

__device__ __forceinline__ void ldsm4(unsigned& r0, unsigned& r1, unsigned& r2,
                                      unsigned& r3, unsigned addr) {
    asm volatile("ldmatrix.sync.aligned.m8n8.x4.shared.b16 {%0,%1,%2,%3}, [%4];"
                 : "=r"(r0), "=r"(r1), "=r"(r2), "=r"(r3) : "r"(addr));
}

__device__ __forceinline__ void cpa16(unsigned dst, const void* src) {
    asm volatile("cp.async.ca.shared.global [%0], [%1], 16;" :: "r"(dst), "l"(src));
}
#define CP_COMMIT asm volatile("cp.async.commit_group;" ::: "memory")
#define CP_WAIT(n) asm volatile("cp.async.wait_group %0;" :: "n"(n) : "memory")

// ================= fused prep kernel =================
// blocks [0, 1056): xi transpose, one per (b, cq, hp).
// blocks [1056, 1520): weights, 2048 elems each (950272 = 464 blocks).
#define XI_BLOCKS 1056
extern "C" __global__ void prep_kernel(const float* __restrict__ xi,
                                       const float* __restrict__ W0,
                                       const float* __restrict__ W1,
                                       const float* __restrict__ W2) {
    const int tid = threadIdx.x;
    if (blockIdx.x < XI_BLOCKS) {
        __shared__ __half smT[32][134];            // [kc][wp]
        const int bi = blockIdx.x;
        const int hp = bi % 132;
        const int t  = bi / 132;
        const int cq = t & 3, b = t >> 2;
        const int h  = hp - 2;
        const bool hok = (unsigned)h < IMH;
        if (tid < 32) {
            smT[tid][0] = __half(0); smT[tid][1] = __half(0);
            smT[tid][130] = __half(0); smT[tid][131] = __half(0);
        }
        const int w = tid & 127, cl0 = tid >> 7;   // 2 channel-rows per pass
        for (int cc = 0; cc < 32; cc += 2) {
            const int cl = cc + cl0;
            float v = 0.f;
            if (hok)
                v = xi[(((size_t)b * FC + cq * 32 + cl) * IMH + h) * IMW + w];
            smT[cl][w + 2] = __float2half_rn(v);
        }
        __syncthreads();
        __half2* dst2 = (__half2*)(g_xiA + ((size_t)bi) * (132 * 32));
        for (int r2 = tid; r2 < 132 * 16; r2 += THREADS) {
            const int kc2 = r2 & 15, wa = r2 >> 4;
            dst2[r2] = __halves2half2(smT[2 * kc2][wa], smT[2 * kc2 + 1][wa]);
        }
    } else {
        const int base = (blockIdx.x - XI_BLOCKS) * 2048;
        const int NW0 = 25 * 4 * 256 * 32;         // 819200
#pragma unroll
        for (int l = 0; l < 8; ++l) {
            const int idx = base + l * 256 + tid;
            if (idx < NW0) {
                const int kc = idx & 31, n = (idx >> 5) & 255;
                const int cq = (idx >> 13) & 3, tap = idx >> 15;
                const int c = cq * 32 + kc;
                g_W0s[idx] = __float2half_rn(W0[((size_t)c * 25 + tap) * HID + n] * WSCALE);
            } else {
                int r = idx - NW0;
                if (r < 2 * 65536) {
                    const int which = r >> 16; r &= 65535;
                    const int kc = r & 31, n = (r >> 5) & 255, kb = r >> 13;
                    const int k = kb * 32 + kc;
                    const float v = (which ? W2 : W1)[(size_t)k * HID + n] * WSCALE;
                    if (which) g_W2s[r] = __float2half_rn(v);
                    else       g_W1s[r] = __float2half_rn(v);
                }
            }
        }
    }
}

// ================= main fused kernel =================
extern "C" __global__ void __launch_bounds__(THREADS, 2)
nerd_fused_kernel(const float* __restrict__ W0f, const float* __restrict__ b0,
                  const float* __restrict__ b1, const float* __restrict__ b2,
                  const float* __restrict__ W3, const float* __restrict__ b3,
                  float* __restrict__ out)
{
    extern __shared__ __half smem[];
    __half* smH = smem;                              // [64][264]
    const unsigned sbase = (unsigned)__cvta_generic_to_shared(smem);

    const int tid  = threadIdx.x;
    const int lane = tid & 31, warp = tid >> 5;      // 8 warps, all share M=64
    const int wn = warp;                             // warp n block of 32
    const int lr = lane >> 2, lc = lane & 3;
    const int l15 = lane & 15, lhi = lane >> 4;
    const int bx = blockIdx.x;
    const int bimg  = bx >> 8;
    const int hrow  = (bx & 255) >> 1;
    const int mhalf = bx & 1;

    float acc[64];                                   // [mt4][np2][q2][4]
#pragma unroll
    for (int i = 0; i < 64; ++i) acc[i] = 0.f;

    // ---- per-thread address constants (bytes) ----
    unsigned aRow[4], bRow[2];
#pragma unroll
    for (int mt = 0; mt < 4; ++mt)
        aRow[mt] = ((mt * 16 + l15) * SMA_H + lhi * 8) * 2;
#pragma unroll
    for (int np = 0; np < 2; ++np)
        bRow[np] = ((wn * 32 + np * 16 + l15) * SMB_H + lhi * 8) * 2;
    const unsigned Bbuf0 = sbase + OFF_B(0) * 2;
    const unsigned aBuf0 = sbase;
    const unsigned stB_d = ((tid >> 2) * SMB_H + (tid & 3) * 8) * 2;
    const unsigned stA_d = ((tid >> 2) * SMA_H + (tid & 3) * 8) * 2;

    // ---- staging (K=32 slabs) ----
    auto stage_B = [&](const __half* src, unsigned bufB) {   // 1024 chunks
        unsigned d = bufB + stB_d;
        const __half* sp = src + (size_t)tid * 8;
#pragma unroll
        for (int l = 0; l < 4; ++l) {
            cpa16(d, sp);
            d += 64 * SMB_H * 2;                     // +64 n-rows
            sp += 2048;                              // +256 chunks
        }
    };
    auto stage_A = [&](const __half* src, unsigned bufB) {   // 272 chunks (68 rows)
        unsigned d = bufB + stA_d;
        const __half* sp = src + (size_t)tid * 8;
        cpa16(d, sp);                                // l = 0 (tid < 256)
        if (tid < 16)                                // l = 1: chunks 256..271
            cpa16(d + 64 * SMA_H * 2, sp + 2048);
    };
    auto aSrc = [&](int g) {                         // g = ph*4 + cq
        const int ph = g >> 2, cq = g & 3;
        return g_xiA + ((size_t)((bimg * 4 + cq) * 132 + hrow + ph)) * (132 * 32)
                     + (size_t)mhalf * 64 * 32;
    };
    auto bSrc0 = [&](int g, int pw) {
        const int ph = g >> 2, cq = g & 3;
        return g_W0s + ((size_t)((ph * 5 + pw) * 4 + cq)) * 8192;
    };

    // ---- prologue ----
    stage_A(aSrc(0), aBuf0); stage_B(bSrc0(0, 0), Bbuf0); CP_COMMIT;
    stage_B(bSrc0(0, 1), Bbuf0 + SMB_HALF * 2); CP_COMMIT;

    unsigned af[4][4], bf[2][4];

    // ================= Layer 0: 100 K=32 slabs (g=ph*4+cq, pw) ==============
    int cur3 = 0, nxt3 = 2;
    for (int g = 0; g < 20; ++g) {
        const unsigned aBufB = aBuf0 + (g & 1) * (SMA_HALF * 2);
#pragma unroll 1
        for (int pw = 0; pw < 5; ++pw) {
            const int s = g * 5 + pw;
            CP_WAIT(1);
            __syncthreads();
            if (s + 2 < 100) {
                const int s2 = s + 2, gg2 = s2 / 5, pw2 = s2 - gg2 * 5;
                stage_B(bSrc0(gg2, pw2), Bbuf0 + nxt3 * (SMB_HALF * 2));
            }
            if (pw == 3 && g + 1 < 20)
                stage_A(aSrc(g + 1), aBuf0 + ((g + 1) & 1) * (SMA_HALF * 2));
            CP_COMMIT;

            unsigned aAd[4], bAd[2];
            const unsigned aPw = aBufB + pw * (SMA_H * 2);
            const unsigned bBufB = Bbuf0 + cur3 * (SMB_HALF * 2);
#pragma unroll
            for (int mt = 0; mt < 4; ++mt) aAd[mt] = aPw + aRow[mt];
#pragma unroll
            for (int np = 0; np < 2; ++np) bAd[np] = bBufB + bRow[np];

#pragma unroll
            for (int kk = 0; kk < 2; ++kk) {
#pragma unroll
                for (int mt = 0; mt < 4; ++mt)
                    ldsm4(af[mt][0], af[mt][1], af[mt][2], af[mt][3],
                          aAd[mt] + kk * 32);
#pragma unroll
                for (int np = 0; np < 2; ++np)
                    ldsm4(bf[np][0], bf[np][1], bf[np][2], bf[np][3],
                          bAd[np] + kk * 32);
#pragma unroll
                for (int np = 0; np < 2; ++np)
#pragma unroll
                    for (int mt = 0; mt < 4; ++mt) {
                        mma16(&acc[((mt * 2 + np) * 2 + 0) * 4], af[mt], bf[np][0], bf[np][2]);
                        mma16(&acc[((mt * 2 + np) * 2 + 1) * 4], af[mt], bf[np][1], bf[np][3]);
                    }
            }
            cur3 = (cur3 == 2) ? 0 : cur3 + 1;
            nxt3 = (nxt3 == 2) ? 0 : nxt3 + 1;
        }
    }
    CP_WAIT(0);
    __syncthreads();

    // ---- layer-0 epilogue: acc/256 + coords + b0, sin -> smH (fp16) ----
    {
        const float gy = -1.f + 2.f * (float)hrow * (1.f / 127.f);
#pragma unroll
        for (int mt = 0; mt < 4; ++mt)
#pragma unroll
            for (int np = 0; np < 2; ++np)
#pragma unroll
                for (int q = 0; q < 2; ++q)
#pragma unroll
                    for (int hf = 0; hf < 2; ++hf) {
                        const int m = mt * 16 + lr + hf * 8;        // local 0..63
                        const int n0 = wn * 32 + np * 16 + q * 8 + lc * 2;
                        const int mg = mhalf * 64 + m;
                        const float gx = -1.f + 2.f * (float)mg * (1.f / 127.f);
                        const int ai = ((mt * 2 + np) * 2 + q) * 4 + hf * 2;
                        const float z0 = acc[ai] * INV_WSCALE
                                       + gx * W0f[3200 * HID + n0] + gy * W0f[3201 * HID + n0] + b0[n0];
                        const float z1 = acc[ai + 1] * INV_WSCALE
                                       + gx * W0f[3200 * HID + n0 + 1] + gy * W0f[3201 * HID + n0 + 1] + b0[n0 + 1];
                        *(__half2*)(smH + m * SMH_H + n0) =
                            __floats2half2_rn(__sinf(OMEGA * z0), __sinf(OMEGA * z1));
                    }
    }
    __syncthreads();

    // ================= Layers 1 and 2: 8 K=32 slabs each =====================
    unsigned aRowH[4];
#pragma unroll
    for (int mt = 0; mt < 4; ++mt)
        aRowH[mt] = sbase + ((mt * 16 + l15) * SMH_H + lhi * 8) * 2;

    for (int L = 0; L < 2; ++L) {
        const __half* Ws = L ? g_W2s : g_W1s;
        const float* bl = L ? b2 : b1;
#pragma unroll
        for (int i = 0; i < 64; ++i) acc[i] = 0.f;

        stage_B(Ws, Bbuf0); CP_COMMIT;
        stage_B(Ws + 8192, Bbuf0 + SMB_HALF * 2); CP_COMMIT;

        cur3 = 0; nxt3 = 2;
#pragma unroll 1
        for (int kb = 0; kb < 8; ++kb) {
            CP_WAIT(1);
            __syncthreads();
            if (kb + 2 < 8) stage_B(Ws + (size_t)(kb + 2) * 8192, Bbuf0 + nxt3 * (SMB_HALF * 2));
            CP_COMMIT;

            unsigned aAd[4], bAd[2];
            const unsigned bBufB = Bbuf0 + cur3 * (SMB_HALF * 2);
#pragma unroll
            for (int mt = 0; mt < 4; ++mt) aAd[mt] = aRowH[mt] + kb * 64;   // 32 halves
#pragma unroll
            for (int np = 0; np < 2; ++np) bAd[np] = bBufB + bRow[np];

#pragma unroll
            for (int kk = 0; kk < 2; ++kk) {
#pragma unroll
                for (int mt = 0; mt < 4; ++mt)
                    ldsm4(af[mt][0], af[mt][1], af[mt][2], af[mt][3],
                          aAd[mt] + kk * 32);
#pragma unroll
                for (int np = 0; np < 2; ++np)
                    ldsm4(bf[np][0], bf[np][1], bf[np][2], bf[np][3],
                          bAd[np] + kk * 32);
#pragma unroll
                for (int np = 0; np < 2; ++np)
#pragma unroll
                    for (int mt = 0; mt < 4; ++mt) {
                        mma16(&acc[((mt * 2 + np) * 2 + 0) * 4], af[mt], bf[np][0], bf[np][2]);
                        mma16(&acc[((mt * 2 + np) * 2 + 1) * 4], af[mt], bf[np][1], bf[np][3]);
                    }
            }
            cur3 = (cur3 == 2) ? 0 : cur3 + 1;
            nxt3 = (nxt3 == 2) ? 0 : nxt3 + 1;
        }
        CP_WAIT(0);
        __syncthreads();

        // epilogue: acc/256 + bl, sin -> smH
#pragma unroll
        for (int mt = 0; mt < 4; ++mt)
#pragma unroll
            for (int np = 0; np < 2; ++np)
#pragma unroll
                for (int q = 0; q < 2; ++q)
#pragma unroll
                    for (int hf = 0; hf < 2; ++hf) {
                        const int m = mt * 16 + lr + hf * 8;
                        const int n0 = wn * 32 + np * 16 + q * 8 + lc * 2;
                        const int ai = ((mt * 2 + np) * 2 + q) * 4 + hf * 2;
                        const float z0 = acc[ai] * INV_WSCALE + bl[n0];
                        const float z1 = acc[ai + 1] * INV_WSCALE + bl[n0 + 1];
                        *(__half2*)(smH + m * SMH_H + n0) =
                            __floats2half2_rn(__sinf(OMEGA * z0), __sinf(OMEGA * z1));
                    }
        __syncthreads();
    }

    // ================= Head: [64 x 256] @ [256 x 3] + b3 =================
    if (tid < 64 * OUTC) {
        const int p = tid % 64, o = tid / 64;
        float sum = b3[o];
#pragma unroll 4
        for (int k = 0; k < HID; k += 2) {
            const float2 f = __half22float2(*(const __half2*)(smH + p * SMH_H + k));
            sum += f.x * W3[k * OUTC + o] + f.y * W3[(k + 1) * OUTC + o];
        }
        const int pg = mhalf * 64 + p;
        out[(((size_t)bimg * OUTC + o) * IMH + hrow) * IMW + pg] = sum;
    }
}

extern "C" void kernel_launch(void* const* d_in, const int* in_sizes, int n_in,
                              void* d_out, int out_size)
{
    const float* xi = (const float*)d_in[0];
    const float* W0 = (const float*)d_in[1];
    const float* b0 = (const float*)d_in[2];
    const float* W1 = (const float*)d_in[3];
    const float* b1 = (const float*)d_in[4];
    const float* W2 = (const float*)d_in[5];
    const float* b2 = (const float*)d_in[6];
    const float* W3 = (const float*)d_in[7];
    const float* b3 = (const float*)d_in[8];
    float* out = (float*)d_out;

    cudaFuncSetAttribute(nerd_fused_kernel,
                         cudaFuncAttributeMaxDynamicSharedMemorySize, SMEM_BYTES);

    prep_kernel<<<XI_BLOCKS + 464, THREADS>>>(xi, W0, W1, W2);
    nerd_fused_kernel<<<512, THREADS, SMEM_BYTES>>>(W0, b0, b1, b2, W3, b3, out);
}